// round 1
// baseline (speedup 1.0000x reference)
#include <cuda_runtime.h>
#include <cuda_bf16.h>

// Problem constants (from reference_code)
#define Bn   2
#define NH   8
#define KW   5
#define KK   25       // KW*KW neighbor offsets
#define HD   16       // head_dim = 128/8
#define HC   48       // coarse H
#define WC   48       // coarse W
#define OH   96       // query_height
#define OW   96       // query_width
// scale_factor = 2, dilation = 1, radius = 2

// Output layout: concat(k_nb, v_nb, mask) flattened, all planes are 96*96=9216 floats.
//   k_nb planes:  [0, 6400)          plane p = ((b*NH + h)*KK + kk)*HD + d
//   v_nb planes:  [6400, 12800)
//   mask planes:  [12800, 13200)     plane p = (b*NH + h)*KK + kk
// Global float offset of plane P is P*9216 uniformly.

constexpr int PLANE_KV        = Bn * NH * KK * HD;       // 6400
constexpr int PLANE_MASK_BASE = 2 * PLANE_KV;            // 12800
constexpr int PLANES          = PLANE_MASK_BASE + Bn * NH * KK; // 13200
constexpr int Q4_PER_ROW      = OW / 4;                  // 24 float4 per row
constexpr int ITEMS_PER_PLANE = OH * Q4_PER_ROW;         // 2304 float4 per plane
constexpr int TOTAL_ITEMS     = PLANES * ITEMS_PER_PLANE; // 30,412,800

__global__ void __launch_bounds__(256)
xsn_extract_kernel(const float* __restrict__ kin,
                   const float* __restrict__ vin,
                   float* __restrict__ out)
{
    int tid = blockIdx.x * 256 + threadIdx.x;
    if (tid >= TOTAL_ITEMS) return;

    int plane = tid / ITEMS_PER_PLANE;
    int item  = tid - plane * ITEMS_PER_PLANE;
    int row   = item / Q4_PER_ROW;            // fine row 0..95
    int qx    = item - row * Q4_PER_ROW;      // float4 index in row, 0..23

    // Decode which tensor & plane-local indices
    const float* src = kin;
    int p = plane;
    bool is_mask = false;
    if (plane >= PLANE_MASK_BASE) {
        is_mask = true;
        p = plane - PLANE_MASK_BASE;
    } else if (plane >= PLANE_KV) {
        src = vin;
        p = plane - PLANE_KV;
    }

    int kk, base = 0;
    if (is_mask) {
        kk = p % KK;                           // p = bh*25 + kk
    } else {
        int d    = p & (HD - 1);               // p = (bh*25 + kk)*16 + d
        int rest = p >> 4;
        kk       = rest % KK;
        int bh   = rest / KK;                  // b*NH + h
        base     = (bh * HD + d) * (HC * WC);  // channel = bh*16 + d
    }

    int dy = kk / KW - 2;
    int dx = kk - (kk / KW) * KW - 2;

    int yc  = (row >> 1) + dy;                 // coarse row + offset
    int xc0 = (qx << 1) + dx;                  // two coarse cols this thread covers
    int xc1 = xc0 + 1;

    bool vy  = (unsigned)yc  < (unsigned)HC;
    bool vx0 = vy && ((unsigned)xc0 < (unsigned)WC);
    bool vx1 = vy && ((unsigned)xc1 < (unsigned)WC);

    float v0, v1;
    if (is_mask) {
        v0 = vx0 ? 1.0f : 0.0f;
        v1 = vx1 ? 1.0f : 0.0f;
    } else {
        const float* rowp = src + base + yc * WC;
        v0 = vx0 ? __ldg(rowp + xc0) : 0.0f;
        v1 = vx1 ? __ldg(rowp + xc1) : 0.0f;
    }

    // Fine x replication: {v(c), v(c), v(c+1), v(c+1)}; out float4 index == tid.
    float4 o = make_float4(v0, v0, v1, v1);
    reinterpret_cast<float4*>(out)[tid] = o;
}

extern "C" void kernel_launch(void* const* d_in, const int* in_sizes, int n_in,
                              void* d_out, int out_size)
{
    const float* k = (const float*)d_in[0];
    const float* v = (const float*)d_in[1];
    float* out = (float*)d_out;

    int blocks = (TOTAL_ITEMS + 255) / 256;   // 118,800
    xsn_extract_kernel<<<blocks, 256>>>(k, v, out);
}

// round 3
// speedup vs baseline: 1.3008x; 1.3008x over previous
#include <cuda_runtime.h>
#include <cuda_bf16.h>

// Problem constants (from reference_code)
#define Bn   2
#define NH   8
#define KW   5
#define KK   25       // 5x5 neighbor offsets
#define HD   16       // head_dim = 128/8
#define HC   48       // coarse H
#define WC   48       // coarse W
#define OH   96       // query_height
#define OW   96       // query_width
// scale_factor = 2, dilation = 1, radius = 2

// Output layout: concat(k_nb, v_nb, mask); every plane is 96*96 = 9216 floats.
//   k_nb planes:  [0, 6400)        plane p = ((b*NH + h)*KK + kk)*HD + d
//   v_nb planes:  [6400, 12800)
//   mask planes:  [12800, 13200)   plane p = (b*NH + h)*KK + kk
constexpr int PLANE_KV        = Bn * NH * KK * HD;            // 6400
constexpr int PLANE_MASK_BASE = 2 * PLANE_KV;                 // 12800
constexpr int PLANES          = PLANE_MASK_BASE + Bn * NH * KK; // 13200

constexpr int Q4_PER_ROW   = OW / 4;          // 24 float4 per fine row
constexpr int CROWS        = HC;              // 48 coarse rows per plane
constexpr int ITEMS        = CROWS * Q4_PER_ROW; // 1152 coarse items per plane
constexpr int TPB          = 288;             // 1152 / 288 = 4 blocks per plane
constexpr int BLKX         = ITEMS / TPB;     // 4

__global__ void __launch_bounds__(TPB)
xsn_extract_kernel(const float* __restrict__ kin,
                   const float* __restrict__ vin,
                   float* __restrict__ out)
{
    // ---- block-uniform plane decode ----
    const int plane = blockIdx.y;

    const float* src = kin;
    int p = plane;
    bool is_mask = false;
    if (plane >= PLANE_MASK_BASE) {
        is_mask = true;
        p = plane - PLANE_MASK_BASE;
    } else if (plane >= PLANE_KV) {
        src = vin;
        p = plane - PLANE_KV;
    }

    int kk, base = 0;
    if (is_mask) {
        kk = p % KK;                           // p = bh*25 + kk
    } else {
        int d    = p & (HD - 1);               // p = (bh*25 + kk)*16 + d
        int rest = p >> 4;
        kk       = rest % KK;
        int bh   = rest / KK;                  // b*NH + h
        base     = (bh * HD + d) * (HC * WC);  // channel = bh*16 + d
    }
    const int dy = kk / KW - 2;
    const int dx = kk - (kk / KW) * KW - 2;

    // ---- per-thread coarse item: one coarse row r, one float4-column qx ----
    const int item = blockIdx.x * TPB + threadIdx.x;   // 0..1151
    const int cr   = item / Q4_PER_ROW;                // coarse row 0..47
    const int qx   = item - cr * Q4_PER_ROW;           // float4 col 0..23

    const int yc  = cr + dy;                           // coarse source row
    const int xc0 = (qx << 1) + dx;                    // two coarse source cols
    const int xc1 = xc0 + 1;

    const bool vy  = (unsigned)yc  < (unsigned)HC;
    const bool vx0 = vy && ((unsigned)xc0 < (unsigned)WC);
    const bool vx1 = vy && ((unsigned)xc1 < (unsigned)WC);

    float v0, v1;
    if (is_mask) {
        v0 = vx0 ? 1.0f : 0.0f;
        v1 = vx1 ? 1.0f : 0.0f;
    } else {
        const float* rowp = src + base + yc * WC;
        v0 = vx0 ? __ldg(rowp + xc0) : 0.0f;
        v1 = vx1 ? __ldg(rowp + xc1) : 0.0f;
    }

    // fine x replication: {v0,v0,v1,v1}; fine rows 2*cr and 2*cr+1 are identical
    const float4 o = make_float4(v0, v0, v1, v1);
    float4* dst = reinterpret_cast<float4*>(out)
                + plane * (OH * Q4_PER_ROW)            // plane * 2304
                + cr * (2 * Q4_PER_ROW)                // fine row 2*cr
                + qx;
    dst[0]          = o;    // fine row 2*cr
    dst[Q4_PER_ROW] = o;    // fine row 2*cr+1
}

extern "C" void kernel_launch(void* const* d_in, const int* in_sizes, int n_in,
                              void* d_out, int out_size)
{
    const float* k = (const float*)d_in[0];
    const float* v = (const float*)d_in[1];
    float* out = (float*)d_out;

    dim3 grid(BLKX, PLANES, 1);   // (4, 13200)
    xsn_extract_kernel<<<grid, TPB>>>(k, v, out);
}

// round 4
// speedup vs baseline: 1.4238x; 1.0946x over previous
#include <cuda_runtime.h>
#include <cuda_bf16.h>

// Problem constants (from reference_code)
#define Bn   2
#define NH   8
#define KW   5
#define KK   25       // 5x5 neighbor offsets
#define HD   16       // head_dim = 128/8
#define HC   48       // coarse H
#define WC   48       // coarse W
#define OH   96       // query_height
#define OW   96       // query_width
// scale_factor = 2, dilation = 1, radius = 2

// Output layout: concat(k_nb, v_nb, mask); every plane is 96*96 = 9216 floats.
//   k_nb planes:  [0, 6400)        plane p = ((b*NH + h)*KK + kk)*HD + d
//   v_nb planes:  [6400, 12800)
//   mask planes:  [12800, 13200)   plane p = (b*NH + h)*KK + kk
constexpr int PLANE_KV        = Bn * NH * KK * HD;              // 6400
constexpr int PLANE_MASK_BASE = 2 * PLANE_KV;                   // 12800
constexpr int PLANES          = PLANE_MASK_BASE + Bn * NH * KK; // 13200

constexpr int Q4_PER_ROW = OW / 4;              // 24 float4 per fine row
constexpr int ROWS_HALF  = HC / 2;              // 24: each thread does cr and cr+24
constexpr int ITEMS      = ROWS_HALF * Q4_PER_ROW; // 576 items per plane
constexpr int TPB        = 288;                 // 576 / 288 = 2 blocks per plane
constexpr int BLKX       = ITEMS / TPB;         // 2

__device__ __forceinline__ void stcs4(float4* p, float4 v) {
    asm volatile("st.global.cs.v4.f32 [%0], {%1, %2, %3, %4};"
                 :: "l"(p), "f"(v.x), "f"(v.y), "f"(v.z), "f"(v.w) : "memory");
}

__global__ void __launch_bounds__(TPB)
xsn_extract_kernel(const float* __restrict__ kin,
                   const float* __restrict__ vin,
                   float* __restrict__ out)
{
    // ---- block-uniform plane decode ----
    const int plane = blockIdx.y;

    const float* src = kin;
    int p = plane;
    bool is_mask = false;
    if (plane >= PLANE_MASK_BASE) {
        is_mask = true;
        p = plane - PLANE_MASK_BASE;
    } else if (plane >= PLANE_KV) {
        src = vin;
        p = plane - PLANE_KV;
    }

    int kk, base = 0;
    if (is_mask) {
        kk = p % KK;                           // p = bh*25 + kk
    } else {
        int d    = p & (HD - 1);               // p = (bh*25 + kk)*16 + d
        int rest = p >> 4;
        kk       = rest % KK;
        int bh   = rest / KK;                  // b*NH + h
        base     = (bh * HD + d) * (HC * WC);  // channel = bh*16 + d
    }
    const int dy = kk / KW - 2;
    const int dx = kk - (kk / KW) * KW - 2;

    // ---- per-thread: one float4-column qx, two coarse rows (cr, cr+24) ----
    const int item = blockIdx.x * TPB + threadIdx.x;   // 0..575
    const int cr   = item / Q4_PER_ROW;                // coarse row 0..23
    const int qx   = item - cr * Q4_PER_ROW;           // float4 col 0..23

    const int xc0 = (qx << 1) + dx;                    // two coarse source cols
    const int xc1 = xc0 + 1;
    const bool bx0 = (unsigned)xc0 < (unsigned)WC;
    const bool bx1 = (unsigned)xc1 < (unsigned)WC;

    const int ycA = cr + dy;                           // coarse source rows
    const int ycB = cr + ROWS_HALF + dy;
    const bool vyA = (unsigned)ycA < (unsigned)HC;
    const bool vyB = (unsigned)ycB < (unsigned)HC;

    float a0, a1, b0, b1;
    if (is_mask) {
        a0 = (vyA && bx0) ? 1.0f : 0.0f;
        a1 = (vyA && bx1) ? 1.0f : 0.0f;
        b0 = (vyB && bx0) ? 1.0f : 0.0f;
        b1 = (vyB && bx1) ? 1.0f : 0.0f;
    } else {
        const float* rowA = src + base + ycA * WC;
        const float* rowB = src + base + ycB * WC;
        a0 = (vyA && bx0) ? __ldg(rowA + xc0) : 0.0f;
        a1 = (vyA && bx1) ? __ldg(rowA + xc1) : 0.0f;
        b0 = (vyB && bx0) ? __ldg(rowB + xc0) : 0.0f;
        b1 = (vyB && bx1) ? __ldg(rowB + xc1) : 0.0f;
    }

    const float4 oA = make_float4(a0, a0, a1, a1);
    const float4 oB = make_float4(b0, b0, b1, b1);

    // fine rows 2*cr, 2*cr+1 (copy A) and 2*(cr+24), 2*(cr+24)+1 (copy B)
    float4* dst = reinterpret_cast<float4*>(out)
                + plane * (OH * Q4_PER_ROW)            // plane * 2304
                + cr * (2 * Q4_PER_ROW)
                + qx;
    stcs4(dst,                               oA);
    stcs4(dst + Q4_PER_ROW,                  oA);
    stcs4(dst + 2 * ROWS_HALF * Q4_PER_ROW,      oB);  // +1152
    stcs4(dst + (2 * ROWS_HALF + 1) * Q4_PER_ROW, oB); // +1176
}

extern "C" void kernel_launch(void* const* d_in, const int* in_sizes, int n_in,
                              void* d_out, int out_size)
{
    const float* k = (const float*)d_in[0];
    const float* v = (const float*)d_in[1];
    float* out = (float*)d_out;

    dim3 grid(BLKX, PLANES, 1);   // (2, 13200)
    xsn_extract_kernel<<<grid, TPB>>>(k, v, out);
}